// round 13
// baseline (speedup 1.0000x reference)
#include <cuda_runtime.h>

#define BB 32
#define TT 2048
#define CC 2048
#define EE 64
#define SEG 16
#define TCHUNK (TT / SEG)          // 128
#define C4 (CC / 4)                // 512
#define E4N (EE / 4)               // 16
#define TQ 64                      // t-rows per k3 block -> 1024 blocks

#define BTE (BB * TT * EE)         // 4194304 = 2^22
#define FB_OFF  BTE                // 4194304
#define LOG_OFF (BTE + 1)          // 4194305
#define MASK_OFF (BTE + 1 + BB * EE) // 4196353 (== 1 mod 4)

// Scratch (no cudaMalloc allowed)
__device__ float g_partials[SEG * BB * CC];   // 2 MB
__device__ float g_dotx[2 * BB * EE];         // per-half-row expert dots
__device__ float g_sscol[2 * EE];             // sim column sumsq per half
__device__ float g_sumsqx[2 * BB];            // ||rep||^2 per half

// ---------------------------------------------------------------------------
// Kernel 1: partial sums of hidden_states over T (round-8 version, measured
// 80.1us @ 85% DRAM = at HBM/LTS cap). Plain loads. No election, no tail.
// ---------------------------------------------------------------------------
__global__ void __launch_bounds__(256)
k1_partial_sums(const float* __restrict__ hs, float* __restrict__ out) {
    if (blockIdx.x == 0 && blockIdx.y == 0 && blockIdx.z == 0 && threadIdx.x == 0)
        out[FB_OFF] = 0.0f;

    const int c4  = blockIdx.x * 256 + threadIdx.x;   // 0..511
    const int b   = blockIdx.y;
    const int seg = blockIdx.z;

    const float4* __restrict__ hs4 = (const float4*)hs;
    size_t base = ((size_t)b * TT + (size_t)seg * TCHUNK) * C4 + (size_t)c4;

    float4 acc = make_float4(0.f, 0.f, 0.f, 0.f);
#pragma unroll 8
    for (int t = 0; t < TCHUNK; ++t) {
        float4 v = hs4[base + (size_t)t * C4];
        acc.x += v.x; acc.y += v.y; acc.z += v.z; acc.w += v.w;
    }
    ((float4*)g_partials)[((size_t)seg * BB + b) * C4 + c4] = acc;
}

// ---------------------------------------------------------------------------
// Kernel 2: half-row reduce + GEMV. grid = (2, BB) = 64 blocks x 256 threads.
// Block (x,b): sums the 16 seg partials for its 1024-c half, computes
// sumsq half + dot[e] half (fixed order -> deterministic); b==0 also the
// sim column-norm half. Separate kernel (round 12 proved the same work as a
// k1 tail is fully exposed; standalone it's ~2-3us).
// ---------------------------------------------------------------------------
__global__ void __launch_bounds__(256)
k2_half_gemv(const float* __restrict__ sim) {
    __shared__ float repc[1024];      // 4 KB
    __shared__ float red[256];
    __shared__ float dots4[4][EE];
    __shared__ float ss4[4][EE];

    const int x   = blockIdx.x;       // 0..1  (c half)
    const int b   = blockIdx.y;
    const int tid = threadIdx.x;
    const int c4  = x * 256 + tid;    // 0..511

    // ---- rep half-chunk + sumsq half ----
    {
        float4 s = make_float4(0.f, 0.f, 0.f, 0.f);
#pragma unroll
        for (int p = 0; p < SEG; ++p) {
            float4 v = ((const float4*)g_partials)[((size_t)p * BB + b) * C4 + c4];
            s.x += v.x; s.y += v.y; s.z += v.z; s.w += v.w;
        }
        const float inv = 1.0f / TT;
        s.x *= inv; s.y *= inv; s.z *= inv; s.w *= inv;
        ((float4*)repc)[tid] = s;
        red[tid] = s.x * s.x + s.y * s.y + s.z * s.z + s.w * s.w;
    }
    __syncthreads();
    for (int ofs = 128; ofs > 0; ofs >>= 1) {
        if (tid < ofs) red[tid] += red[tid + ofs];
        __syncthreads();
    }
    if (tid == 0) g_sumsqx[x * BB + b] = red[0];

    // ---- GEMV over this 1024-c half: e = tid&63, 4 c-groups of 256 ----
    const int e  = tid & (EE - 1);
    const int cg = tid >> 6;
    const int cbase = x * 1024 + cg * 256;
    float dot = 0.f, ss = 0.f;
#pragma unroll 8
    for (int j = 0; j < 256; ++j) {
        float sv = sim[(size_t)(cbase + j) * EE + e];   // coalesced over e
        dot = fmaf(repc[cg * 256 + j], sv, dot);        // LDS broadcast
        ss  = fmaf(sv, sv, ss);
    }
    dots4[cg][e] = dot;
    ss4[cg][e]  = ss;
    __syncthreads();

    if (tid < EE) {
        g_dotx[(x * BB + b) * EE + tid] =
            dots4[0][tid] + dots4[1][tid] + dots4[2][tid] + dots4[3][tid];
        if (b == 0)
            g_sscol[x * EE + tid] =
                ss4[0][tid] + ss4[1][tid] + ss4[2][tid] + ss4[3][tid];
    }
}

// ---------------------------------------------------------------------------
// Kernel 3: finish + broadcast, grid = (BB, TT/TQ) = (32,32) = 1024 blocks
// (measured: 512 blocks -> occ 37% -> latency-bound; 1024 -> ~87% occ).
// Every block redundantly finishes the gating from the two half-row results
// (~70 L2 loads + warp softmax, fixed order -> bit-identical -> determinis-
// tic), then streams its TQ-row chunk. Only yc==0 writes logits/fallback.
// ---------------------------------------------------------------------------
__global__ void __launch_bounds__(256)
k3_finish_broadcast(const float* __restrict__ gates, float* __restrict__ out) {
    __shared__ float logits_s[EE];
    __shared__ float msk[EE];
    __shared__ float probs_s[EE];
    __shared__ float sm_max, sm_sum;

    const int b   = blockIdx.x;
    const int yc  = blockIdx.y;
    const int tid = threadIdx.x;

    // ---- finish gating (cheap, redundant per block) ----
    float l = 0.f;
    if (tid < EE) {
        float d  = g_dotx[b * EE + tid] + g_dotx[(BB + b) * EE + tid];
        float ss = g_sscol[tid] + g_sscol[EE + tid];
        float sq = g_sumsqx[b] + g_sumsqx[BB + b];
        float nrep = fmaxf(sqrtf(sq), 1e-12f);
        float ncol = fmaxf(sqrtf(ss), 1e-12f);
        float aff  = d / (nrep * ncol);
        float gv   = gates[tid];
        float sig  = 1.0f / (1.0f + __expf(-gv));
        l = aff - sig;
        logits_s[tid] = l;
    }
    const int na = __syncthreads_count((tid < EE) && (l > 0.f));
    const int inactive = (na == 0) ? 1 : 0;

    // mask: threshold or top-32 fallback (lax.top_k tie semantics: stable,
    // lowest index wins among equals)
    if (tid < EE) {
        float m;
        if (!inactive) {
            m = (l > 0.f) ? 1.f : 0.f;
        } else {
            int rank = 0;
            for (int j = 0; j < EE; ++j) {
                float lj = logits_s[j];
                rank += ((lj > l) || (lj == l && j < tid)) ? 1 : 0;
            }
            m = (rank < (EE / 2)) ? 1.f : 0.f;
        }
        msk[tid] = m;
    }
    __syncthreads();

    // ---- masked softmax stats: warp 0, butterfly reduce (deterministic) ----
    if (tid < 32) {
        float l1 = logits_s[tid],      l2 = logits_s[tid + 32];
        float g1 = fmaxf(l1, 0.f),     g2 = fmaxf(l2, 0.f);
        bool  a1 = msk[tid] > 0.f,     a2 = msk[tid + 32] > 0.f;
        float mx = fmaxf(a1 ? g1 : -3.402823466e+38f,
                         a2 ? g2 : -3.402823466e+38f);
#pragma unroll
        for (int o = 16; o > 0; o >>= 1)
            mx = fmaxf(mx, __shfl_xor_sync(0xffffffffu, mx, o));
        float s = (a1 ? __expf(g1 - mx) : 0.f) + (a2 ? __expf(g2 - mx) : 0.f);
#pragma unroll
        for (int o = 16; o > 0; o >>= 1)
            s += __shfl_xor_sync(0xffffffffu, s, o);
        if (tid == 0) {
            sm_max = mx;
            sm_sum = s;
            if (yc == 0 && inactive)
                atomicAdd(&out[FB_OFF], 1.0f);  // integer-valued -> deterministic
        }
    }
    __syncthreads();

    if (tid < EE) {
        float gated = fmaxf(l, 0.f);
        probs_s[tid] = (msk[tid] > 0.f) ? (__expf(gated - sm_max) / sm_sum) : 0.f;
        if (yc == 0) out[LOG_OFF + b * EE + tid] = l;   // logits written once
    }
    __syncthreads();

    // ================= broadcast chunk [yc*TQ, yc*TQ+TQ) =================
    const int slot = tid & 15;   // 0..15
    const int trow = tid >> 4;   // 0..15

    const float4 pv = ((const float4*)probs_s)[slot];

    // mask values per slot: slot 0 -> scalars e=0,1,2,63 ; slot s>0 ->
    // aligned float4 at e=4s-1 (MASK_OFF == 1 mod 4)
    float4 mv = make_float4(0.f, 0.f, 0.f, 0.f);
    float m0 = 0.f, m1 = 0.f, m2 = 0.f, m63 = 0.f;
    if (slot == 0) { m0 = msk[0]; m1 = msk[1]; m2 = msk[2]; m63 = msk[63]; }
    else { int e = 4 * slot - 1; mv = make_float4(msk[e], msk[e+1], msk[e+2], msk[e+3]); }

    const size_t brow = (size_t)b * TT * EE;
    const int t0 = yc * TQ;

#pragma unroll
    for (int it = 0; it < TQ / 16; ++it) {
        const size_t row = brow + (size_t)(t0 + it * 16 + trow) * EE;
        __stcs((float4*)(out) + row / 4 + slot, pv);
        if (slot == 0) {
            float* d = out + MASK_OFF + row;
            __stcs(d + 0, m0); __stcs(d + 1, m1); __stcs(d + 2, m2); __stcs(d + 63, m63);
        } else {
            __stcs((float4*)(out + MASK_OFF + row + 4 * slot - 1), mv);
        }
    }
}

// ---------------------------------------------------------------------------
extern "C" void kernel_launch(void* const* d_in, const int* in_sizes, int n_in,
                              void* d_out, int out_size) {
    const float* hs    = (const float*)d_in[0];
    const float* sim   = (const float*)d_in[1];
    const float* gates = (const float*)d_in[2];
    float* out = (float*)d_out;

    k1_partial_sums<<<dim3(C4 / 256, BB, SEG), 256>>>(hs, out);
    k2_half_gemv<<<dim3(2, BB), 256>>>(sim);
    k3_finish_broadcast<<<dim3(BB, TT / TQ), 256>>>(gates, out);
}

// round 14
// speedup vs baseline: 1.0546x; 1.0546x over previous
#include <cuda_runtime.h>

#define BB 32
#define TT 2048
#define CC 2048
#define EE 64
#define SEG 16
#define TCHUNK (TT / SEG)          // 128
#define C4 (CC / 4)                // 512
#define E4N (EE / 4)               // 16
#define TQ 64                      // t-rows per k23 block -> (32,32) grid
#define PARTS 16
#define CPART (CC / PARTS)         // 128

#define BTE (BB * TT * EE)         // 4194304 = 2^22
#define FB_OFF  BTE                // 4194304
#define LOG_OFF (BTE + 1)          // 4194305
#define MASK_OFF (BTE + 1 + BB * EE) // 4196353 (== 1 mod 4)

// Scratch (no cudaMalloc allowed)
__device__ float g_partials[SEG * BB * CC];   // 2 MB
__device__ float g_dots[BB * PARTS * EE];     // 128 KB
__device__ float g_ssum[BB * PARTS * EE];     // 128 KB
__device__ float g_sumsq[BB * PARTS];
__device__ float g_probs_seq[BB * EE];
__device__ float g_mask_seq[BB * EE];
__device__ volatile int g_flag[BB];

// ---------------------------------------------------------------------------
// Kernel 1: partial sums of hidden_states over T (split into SEG chunks).
// Round-8 version verbatim (measured 80-81us @ 85% DRAM = HBM/LTS cap).
// ---------------------------------------------------------------------------
__global__ void k1_partial_sums(const float* __restrict__ hs, float* __restrict__ out) {
    if (blockIdx.x == 0 && blockIdx.y == 0 && blockIdx.z == 0) {
        if (threadIdx.x == 0) out[FB_OFF] = 0.0f;
        if (threadIdx.x < BB) g_flag[threadIdx.x] = 0;
    }

    const int c4  = blockIdx.x * 256 + threadIdx.x;   // 0..511
    const int b   = blockIdx.y;
    const int seg = blockIdx.z;

    const float4* __restrict__ hs4 = (const float4*)hs;
    size_t base = ((size_t)b * TT + (size_t)seg * TCHUNK) * C4 + (size_t)c4;

    float4 acc = make_float4(0.f, 0.f, 0.f, 0.f);
#pragma unroll 8
    for (int t = 0; t < TCHUNK; ++t) {
        float4 v = hs4[base + (size_t)t * C4];
        acc.x += v.x; acc.y += v.y; acc.z += v.z; acc.w += v.w;
    }
    ((float4*)g_partials)[((size_t)seg * BB + b) * C4 + c4] = acc;
}

// ---------------------------------------------------------------------------
// Kernel 2a: stage-1 gating reduction. grid = (PARTS=16, BB=32) = 512 blocks.
// Round-8 version verbatim. Deterministic fixed-order sums.
// ---------------------------------------------------------------------------
__global__ void k2a_partial_gating(const float* __restrict__ sim) {
    __shared__ float rep_s[CPART];
    __shared__ float red[128];
    __shared__ float dots4[4][EE];
    __shared__ float ss4[4][EE];

    const int part = blockIdx.x;
    const int b    = blockIdx.y;
    const int tid  = threadIdx.x;
    const int c0   = part * CPART;

    // rep chunk + partial sumsq
    if (tid < CPART) {
        float s = 0.f;
#pragma unroll
        for (int p = 0; p < SEG; ++p)
            s += g_partials[(size_t)p * BB * CC + (size_t)b * CC + c0 + tid];
        float r = s * (1.0f / TT);
        rep_s[tid] = r;
        red[tid] = r * r;
    }
    __syncthreads();
    for (int ofs = 64; ofs > 0; ofs >>= 1) {
        if (tid < ofs) red[tid] += red[tid + ofs];
        __syncthreads();
    }
    if (tid == 0) g_sumsq[b * PARTS + part] = red[0];

    // partial dot/ss over this c-chunk: e = tid&63, 4 c-groups of 32
    const int e  = tid & (EE - 1);
    const int cg = tid >> 6;
    float dot = 0.f, ss = 0.f;
#pragma unroll 8
    for (int j = 0; j < 32; ++j) {
        int cl = cg * 32 + j;
        float sv = sim[(size_t)(c0 + cl) * EE + e];
        dot = fmaf(rep_s[cl], sv, dot);
        ss  = fmaf(sv, sv, ss);
    }
    dots4[cg][e] = dot;
    ss4[cg][e]  = ss;
    __syncthreads();

    if (tid < EE) {
        g_dots[(size_t)(b * PARTS + part) * EE + tid] =
            dots4[0][tid] + dots4[1][tid] + dots4[2][tid] + dots4[3][tid];
        g_ssum[(size_t)(b * PARTS + part) * EE + tid] =
            ss4[0][tid] + ss4[1][tid] + ss4[2][tid] + ss4[3][tid];
    }
}

// ---------------------------------------------------------------------------
// Kernel 2b+3 fused. grid = (BB, TT/TQ) = (32, 32), 256 threads.
// Round-8 logic verbatim; ONLY change: TQ 128 -> 64 (1024 blocks instead of
// 512 — round-12 measured the 512-block variant occ-limited at 37%).
// Producer (b, y=0): finishes gating from 16 partials, publishes flag;
// consumers spin briefly then broadcast. Producers are bids 0..31 -> wave-1
// resident -> deadlock-free. Deterministic.
// ---------------------------------------------------------------------------
__global__ void k23_gating_broadcast(const float* __restrict__ gates,
                                     float* __restrict__ out) {
    __shared__ float logits_s[EE];
    __shared__ float msk[EE];
    __shared__ float sm_nrep;
    __shared__ float sm_max, sm_sum;

    const int b   = blockIdx.x;
    const int yc  = blockIdx.y;
    const int tid = threadIdx.x;

    if (yc == 0) {
        // ---- finish reductions ----
        if (tid == 0) {
            float s = 0.f;
#pragma unroll
            for (int p = 0; p < PARTS; ++p) s += g_sumsq[b * PARTS + p];
            sm_nrep = sqrtf(s);
        }
        float l = 0.f;
        if (tid < EE) {
            float dot = 0.f, ss = 0.f;
#pragma unroll
            for (int p = 0; p < PARTS; ++p) {
                dot += g_dots[(size_t)(b * PARTS + p) * EE + tid];
                ss  += g_ssum[(size_t)(b * PARTS + p) * EE + tid];
            }
            __syncthreads();   // sm_nrep ready (all threads reach below too)
            float nrep = fmaxf(sm_nrep, 1e-12f);
            float ncol = fmaxf(sqrtf(ss), 1e-12f);
            float aff  = dot / (nrep * ncol);
            float gv   = gates[tid];
            float sig  = 1.0f / (1.0f + __expf(-gv));
            l = aff - sig;
            logits_s[tid] = l;
        } else {
            __syncthreads();
        }

        // ---- activity count ----
        const int na = __syncthreads_count((tid < EE) && (l > 0.f));
        const int inactive = (na == 0) ? 1 : 0;

        // ---- mask: threshold or top-32 fallback (lax.top_k tie semantics:
        //      stable, lowest index wins among equals) ----
        if (tid < EE) {
            float m;
            if (!inactive) {
                m = (l > 0.f) ? 1.f : 0.f;
            } else {
                int rank = 0;
                for (int j = 0; j < EE; ++j) {
                    float lj = logits_s[j];
                    rank += ((lj > l) || (lj == l && j < tid)) ? 1 : 0;
                }
                m = (rank < (EE / 2)) ? 1.f : 0.f;
            }
            msk[tid] = m;
        }
        __syncthreads();

        // ---- masked softmax stats ----
        if (tid == 0) {
            float mx = -3.402823466e+38f;
            for (int e = 0; e < EE; ++e)
                if (msk[e] > 0.f) mx = fmaxf(mx, fmaxf(logits_s[e], 0.f));
            float sum = 0.f;
            for (int e = 0; e < EE; ++e)
                if (msk[e] > 0.f) sum += __expf(fmaxf(logits_s[e], 0.f) - mx);
            sm_max = mx;
            sm_sum = sum;
            if (inactive) atomicAdd(&out[FB_OFF], 1.0f);  // integer-valued -> deterministic
        }
        __syncthreads();

        // ---- publish per-row results, raise flag ----
        if (tid < EE) {
            float gated = fmaxf(l, 0.f);
            float p = (msk[tid] > 0.f) ? (__expf(gated - sm_max) / sm_sum) : 0.f;
            g_probs_seq[b * EE + tid] = p;
            g_mask_seq[b * EE + tid]  = msk[tid];
            out[LOG_OFF + b * EE + tid] = l;
        }
        __threadfence();
        __syncthreads();
        if (tid == 0) g_flag[b] = 1;
    } else {
        if (tid == 0) {
            while (g_flag[b] == 0) { __nanosleep(64); }
        }
        __syncthreads();
        __threadfence();
        if (tid < EE) msk[tid] = g_mask_seq[b * EE + tid];
        __syncthreads();
    }

    // ================= broadcast chunk [yc*TQ, yc*TQ+TQ) =================
    const int slot = tid & 15;   // 0..15
    const int trow = tid >> 4;   // 0..15

    const float4 pv = ((const float4*)g_probs_seq)[b * E4N + slot];

    // mask values per slot: slot 0 -> scalars e=0,1,2,63 ; slot s>0 ->
    // aligned float4 at e=4s-1 (MASK_OFF == 1 mod 4)
    float4 mv = make_float4(0.f, 0.f, 0.f, 0.f);
    float m0 = 0.f, m1 = 0.f, m2 = 0.f, m63 = 0.f;
    if (slot == 0) { m0 = msk[0]; m1 = msk[1]; m2 = msk[2]; m63 = msk[63]; }
    else { int e = 4 * slot - 1; mv = make_float4(msk[e], msk[e+1], msk[e+2], msk[e+3]); }

    const size_t brow = (size_t)b * TT * EE;
    const int t0 = yc * TQ;

#pragma unroll
    for (int it = 0; it < TQ / 16; ++it) {
        const size_t row = brow + (size_t)(t0 + it * 16 + trow) * EE;
        __stcs((float4*)(out) + row / 4 + slot, pv);
        if (slot == 0) {
            float* d = out + MASK_OFF + row;
            __stcs(d + 0, m0); __stcs(d + 1, m1); __stcs(d + 2, m2); __stcs(d + 63, m63);
        } else {
            __stcs((float4*)(out + MASK_OFF + row + 4 * slot - 1), mv);
        }
    }
}

// ---------------------------------------------------------------------------
extern "C" void kernel_launch(void* const* d_in, const int* in_sizes, int n_in,
                              void* d_out, int out_size) {
    const float* hs    = (const float*)d_in[0];
    const float* sim   = (const float*)d_in[1];
    const float* gates = (const float*)d_in[2];
    float* out = (float*)d_out;

    k1_partial_sums<<<dim3(C4 / 256, BB, SEG), 256>>>(hs, out);
    k2a_partial_gating<<<dim3(PARTS, BB), 256>>>(sim);
    k23_gating_broadcast<<<dim3(BB, TT / TQ), 256>>>(gates, out);
}